// round 13
// baseline (speedup 1.0000x reference)
#include <cuda_runtime.h>
#include <cstdint>

// ---------------- static config ----------------
#define PNX 256
#define PNS 128
#define PI_F 3.14159265358979323846f

#define SIGMA_MM   19.108280254777070f
#define INV_SIGMA  (1.0f/19.108280254777070f)
#define FILT_C2    900.91346f
#define FILT_SCALE (1.0f/1024.0f)
#define WIN_NSIG   3.5f
#define NREP       64            // replicas, INTERLEAVED per pixel
#define FFT_BLOCKS 128           // 2 lines/block, co-resident

// ---------------- device scratch ----------------
__device__ float  g_img[PNX * PNX * NREP];  // layout: [pixel][rep]; zero at load
__device__ float  g_imgsum[PNX * PNX];      // reduced image
__device__ float2 g_freq[PNX * PNX];
__device__ unsigned g_bar_count = 0;
__device__ volatile unsigned g_bar_gen = 0;

// ---------------- packed f32x2 helpers (sm_100a) ----------------
__device__ __forceinline__ uint64_t pack2(float lo, float hi) {
    uint64_t r; asm("mov.b64 %0, {%1, %2};" : "=l"(r) : "f"(lo), "f"(hi)); return r;
}
__device__ __forceinline__ void unpack2(uint64_t v, float& lo, float& hi) {
    asm("mov.b64 {%0, %1}, %2;" : "=f"(lo), "=f"(hi) : "l"(v));
}
__device__ __forceinline__ uint64_t fma2(uint64_t a, uint64_t b, uint64_t c) {
    uint64_t r; asm("fma.rn.f32x2 %0, %1, %2, %3;" : "=l"(r) : "l"(a), "l"(b), "l"(c)); return r;
}
__device__ __forceinline__ uint64_t add2(uint64_t a, uint64_t b) {
    uint64_t r; asm("add.rn.f32x2 %0, %1, %2;" : "=l"(r) : "l"(a), "l"(b)); return r;
}

// ---------------- grid barrier (all blocks co-resident) ----------------
__device__ __forceinline__ void grid_barrier(unsigned nblocks) {
    __syncthreads();
    if (threadIdx.x == 0) {
        unsigned gen = g_bar_gen;
        __threadfence();
        if (atomicAdd(&g_bar_count, 1u) == nblocks - 1u) {
            g_bar_count = 0;
            __threadfence();
            g_bar_gen = gen + 1u;
        } else {
            while (g_bar_gen == gen) { }
            __threadfence();
        }
    }
    __syncthreads();
}

// ---------------- FFT helpers (R11 proven config) ----------------
// 256-pt radix-2 Stockham FFT, 128 threads per line, shared twiddles W[128]:
// W[m] = cis(pi*m/128). sign = -1 fwd, +1 inv (unnormalized). Ends in bufA.
__device__ __forceinline__ void fft256(float2* bufA, float2* bufB,
                                       const float2* __restrict__ W,
                                       int j, float sign) {
    float2* x = bufA;
    float2* y = bufB;
#pragma unroll
    for (int st = 0; st < 8; st++) {
        int Ns = 1 << st;
        float2 v0 = x[j];
        float2 v1 = x[j + 128];
        int k = j & (Ns - 1);
        float2 w = W[k << (7 - st)];
        float wy = sign * w.y;
        float2 tv = make_float2(v1.x * w.x - v1.y * wy,
                                v1.x * wy + v1.y * w.x);
        int id = ((j - k) << 1) + k;
        y[id]      = make_float2(v0.x + tv.x, v0.y + tv.y);
        y[id + Ns] = make_float2(v0.x - tv.x, v0.y - tv.y);
        __syncthreads();
        float2* t = x; x = y; y = t;
    }
}

__device__ __forceinline__ void fill_twiddles(float2* W, int tid) {
    if (tid < 128) {
        float s, c;
        sincospif((float)tid * (1.0f / 128.0f), &s, &c);
        W[tid] = make_float2(c, s);
    }
}

__device__ __forceinline__ float freq_coord(int k) {
    return (k < 128) ? (k + 0.5f) * (1.0f / 128.0f)
                     : (k - 255.5f) * (1.0f / 128.0f);
}

// i0e(x) = exp(-x)*I0(x)
__device__ float i0e_dev(float x) {
    if (x > 8.0f) {
        float invx = 1.0f / x;
        float term = 1.0f, sum = 1.0f;
#pragma unroll
        for (int k = 1; k <= 6; k++) {
            float tk = (float)(2 * k - 1);
            term *= tk * tk * invx * (1.0f / (8.0f * (float)k));
            sum  += term;
        }
        return sum * rsqrtf(2.0f * PI_F * x);
    } else {
        float q = 0.25f * x * x;
        float term = 1.0f, sum = 1.0f;
#pragma unroll
        for (int k = 1; k <= 22; k++) {
            float ik = 1.0f / (float)k;
            term *= q * ik * ik;
            sum  += term;
        }
        return sum * __expf(-x);
    }
}

// ---------------- backprojection ----------------
__global__ void k_bp(const float* __restrict__ proj, const float* __restrict__ tof,
                     const float* __restrict__ x1l, const float* __restrict__ y1l,
                     const float* __restrict__ x1r, const float* __restrict__ y1r,
                     const float* __restrict__ x2l, const float* __restrict__ y2l,
                     const float* __restrict__ x2r, const float* __restrict__ y2r,
                     int n) {
    int e = blockIdx.x * blockDim.x + threadIdx.x;
    if (e >= n) return;

    float x1 = 0.5f * (x1l[e] + x1r[e]);
    float y1 = 0.5f * (y1l[e] + y1r[e]);
    float x2 = 0.5f * (x2l[e] + x2r[e]);
    float y2 = 0.5f * (y2l[e] + y2r[e]);
    float ddx = x2 - x1, ddy = y2 - y1;
    float L = sqrtf(ddx * ddx + ddy * ddy);

    float step     = L * (1.0f / (float)PNS);
    float inv_step = (float)PNS / L;
    float center   = 0.5f * L + 0.15f * tof[e];

    float lo = (center - WIN_NSIG * SIGMA_MM) * inv_step - 0.5f;
    float hi = (center + WIN_NSIG * SIGMA_MM) * inv_step - 0.5f;
    int i0 = max(0,   (int)ceilf(lo));
    int i1 = min(127, (int)floorf(hi));
    if (i0 > i1) return;

    // incremental Gaussian weight
    float dz = step * INV_SIGMA;
    float z0 = (((float)i0 + 0.5f) * step - center) * INV_SIGMA;
    float w  = proj[e] * step * __expf(-0.5f * z0 * z0);
    float r  = __expf(-dz * (z0 + 0.5f * dz));
    float c  = __expf(-dz * dz);

    int rep = e & (NREP - 1);             // interleaved replica slot

    float t0f = ((float)i0 + 0.5f) * (1.0f / (float)PNS);
    uint64_t t2   = pack2(t0f, t0f);
    uint64_t dt2  = pack2(1.0f / (float)PNS, 1.0f / (float)PNS);
    uint64_t dd2  = pack2(ddx, ddy);
    uint64_t xy2  = pack2(x1, y1);
    uint64_t h2   = pack2(0.5f, 0.5f);
    uint64_t b2   = pack2(128.0f, 128.0f);

#pragma unroll 8
    for (int i = i0; i <= i1; i++) {
        uint64_t pxy = fma2(t2, dd2, xy2);
        uint64_t gxy = fma2(pxy, h2, b2);
        float gx, gy;
        unpack2(gxy, gx, gy);
        int ix = __float2int_rd(gx);
        int iy = __float2int_rd(gy);
        if ((unsigned)(ix | iy) < 256u)
            atomicAdd(&g_img[(((iy << 8) + ix) << 6) + rep], w);
        w *= r;  r *= c;
        t2 = add2(t2, dt2);
    }
}

// ---------------- replica reduction ----------------
// One thread per pixel: 64 contiguous replicas = 16 float4 loads, zero, write.
__global__ void k_reduce() {
    int p = blockIdx.x * blockDim.x + threadIdx.x;   // pixel index
    float4* base = (float4*)&g_img[p << 6];
    float acc = 0.0f;
#pragma unroll
    for (int q = 0; q < NREP / 4; q++) {
        float4 v = base[q];
        acc += v.x + v.y + v.z + v.w;
        base[q] = make_float4(0.f, 0.f, 0.f, 0.f);
    }
    g_imgsum[p] = acc;
}

// ---------------- fused 2D FFT + filter (persistent; R11 config) ----------------
// 128 blocks x 256 threads; 2 line-groups of 128 threads: g = tid>>7, j = tid&127.
__global__ void k_fft_all(float* __restrict__ out) {
    __shared__ float2 A[2][256];
    __shared__ float2 B[2][256];
    __shared__ float2 W[128];
    int g = threadIdx.x >> 7;
    int j = threadIdx.x & 127;
    int line = blockIdx.x * 2 + g;
    fill_twiddles(W, threadIdx.x);

    // ---- Phase A: row forward FFT (coalesced read of reduced image) ----
    {
        int row = line;
        A[g][j]       = make_float2(g_imgsum[row * PNX + j],       0.0f);
        A[g][j + 128] = make_float2(g_imgsum[row * PNX + j + 128], 0.0f);
        __syncthreads();
        fft256(A[g], B[g], W, j, -1.0f);
        g_freq[row * PNX + j]       = A[g][j];
        g_freq[row * PNX + j + 128] = A[g][j + 128];
    }

    grid_barrier(FFT_BLOCKS);

    // ---- Phase B: column fwd FFT -> filter -> column inv FFT ----
    {
        int c = line;
        A[g][j]       = __ldcg(&g_freq[j * PNX + c]);
        A[g][j + 128] = __ldcg(&g_freq[(j + 128) * PNX + c]);
        __syncthreads();
        fft256(A[g], B[g], W, j, -1.0f);

        float fc  = freq_coord(c);
        float fc2 = fc * fc;
#pragma unroll
        for (int kk = j; kk < 256; kk += 128) {
            float fr = freq_coord(kk);
            float w0 = fmaf(fr, fr, fc2);
            float gn = FILT_SCALE / i0e_dev(w0 * FILT_C2);
            A[g][kk].x *= gn;
            A[g][kk].y *= gn;
        }
        __syncthreads();
        fft256(A[g], B[g], W, j, +1.0f);
        g_freq[j * PNX + c]         = A[g][j];
        g_freq[(j + 128) * PNX + c] = A[g][j + 128];
    }

    grid_barrier(FFT_BLOCKS);

    // ---- Phase C: row inverse FFT -> real output ----
    {
        int row = line;
        A[g][j]       = __ldcg(&g_freq[row * PNX + j]);
        A[g][j + 128] = __ldcg(&g_freq[row * PNX + j + 128]);
        __syncthreads();
        fft256(A[g], B[g], W, j, +1.0f);
        out[row * PNX + j]       = A[g][j].x;
        out[row * PNX + j + 128] = A[g][j + 128].x;
    }
}

// ---------------- launch ----------------
extern "C" void kernel_launch(void* const* d_in, const int* in_sizes, int n_in,
                              void* d_out, int out_size) {
    const float* proj = (const float*)d_in[0];
    const float* tof  = (const float*)d_in[1];
    const float* x1l  = (const float*)d_in[2];
    const float* y1l  = (const float*)d_in[3];
    const float* x1r  = (const float*)d_in[4];
    const float* y1r  = (const float*)d_in[5];
    const float* x2l  = (const float*)d_in[6];
    const float* y2l  = (const float*)d_in[7];
    const float* x2r  = (const float*)d_in[8];
    const float* y2r  = (const float*)d_in[9];
    int n = in_sizes[0];

    k_bp<<<(n + 255) / 256, 256>>>(proj, tof, x1l, y1l, x1r, y1r,
                                   x2l, y2l, x2r, y2r, n);
    k_reduce<<<(PNX * PNX) / 256, 256>>>();
    k_fft_all<<<FFT_BLOCKS, 256>>>((float*)d_out);
}

// round 14
// speedup vs baseline: 1.1020x; 1.1020x over previous
#include <cuda_runtime.h>
#include <cstdint>

// ---------------- static config ----------------
#define PNX 256
#define PNS 128
#define PI_F 3.14159265358979323846f

#define SIGMA_MM   19.108280254777070f
#define INV_SIGMA  (1.0f/19.108280254777070f)
#define FILT_C2    900.91346f
#define FILT_SCALE (1.0f/1024.0f)
#define WIN_NSIG   3.5f
#define NREP       64            // PLANAR replicas: g_img[rep][pixel]
#define FFT_BLOCKS 128           // 2 lines/block, co-resident

// ---------------- device scratch ----------------
__device__ float  g_img[NREP][PNX * PNX];   // zero-init at load; re-zeroed each call
__device__ float  g_imgsum[PNX * PNX];      // reduced image
__device__ float2 g_freq[PNX * PNX];
__device__ unsigned g_bar_count = 0;
__device__ volatile unsigned g_bar_gen = 0;

// ---------------- packed f32x2 helpers (sm_100a) ----------------
__device__ __forceinline__ uint64_t pack2(float lo, float hi) {
    uint64_t r; asm("mov.b64 %0, {%1, %2};" : "=l"(r) : "f"(lo), "f"(hi)); return r;
}
__device__ __forceinline__ void unpack2(uint64_t v, float& lo, float& hi) {
    asm("mov.b64 {%0, %1}, %2;" : "=f"(lo), "=f"(hi) : "l"(v));
}
__device__ __forceinline__ uint64_t fma2(uint64_t a, uint64_t b, uint64_t c) {
    uint64_t r; asm("fma.rn.f32x2 %0, %1, %2, %3;" : "=l"(r) : "l"(a), "l"(b), "l"(c)); return r;
}
__device__ __forceinline__ uint64_t add2(uint64_t a, uint64_t b) {
    uint64_t r; asm("add.rn.f32x2 %0, %1, %2;" : "=l"(r) : "l"(a), "l"(b)); return r;
}

// ---------------- grid barrier (all blocks co-resident) ----------------
__device__ __forceinline__ void grid_barrier(unsigned nblocks) {
    __syncthreads();
    if (threadIdx.x == 0) {
        unsigned gen = g_bar_gen;
        __threadfence();
        if (atomicAdd(&g_bar_count, 1u) == nblocks - 1u) {
            g_bar_count = 0;
            __threadfence();
            g_bar_gen = gen + 1u;
        } else {
            while (g_bar_gen == gen) { }
            __threadfence();
        }
    }
    __syncthreads();
}

// ---------------- FFT helpers (R11 proven config) ----------------
// 256-pt radix-2 Stockham FFT, 128 threads per line, shared twiddles W[128]:
// W[m] = cis(pi*m/128). sign = -1 fwd, +1 inv (unnormalized). Ends in bufA.
__device__ __forceinline__ void fft256(float2* bufA, float2* bufB,
                                       const float2* __restrict__ W,
                                       int j, float sign) {
    float2* x = bufA;
    float2* y = bufB;
#pragma unroll
    for (int st = 0; st < 8; st++) {
        int Ns = 1 << st;
        float2 v0 = x[j];
        float2 v1 = x[j + 128];
        int k = j & (Ns - 1);
        float2 w = W[k << (7 - st)];
        float wy = sign * w.y;
        float2 tv = make_float2(v1.x * w.x - v1.y * wy,
                                v1.x * wy + v1.y * w.x);
        int id = ((j - k) << 1) + k;
        y[id]      = make_float2(v0.x + tv.x, v0.y + tv.y);
        y[id + Ns] = make_float2(v0.x - tv.x, v0.y - tv.y);
        __syncthreads();
        float2* t = x; x = y; y = t;
    }
}

__device__ __forceinline__ void fill_twiddles(float2* W, int tid) {
    if (tid < 128) {
        float s, c;
        sincospif((float)tid * (1.0f / 128.0f), &s, &c);
        W[tid] = make_float2(c, s);
    }
}

__device__ __forceinline__ float freq_coord(int k) {
    return (k < 128) ? (k + 0.5f) * (1.0f / 128.0f)
                     : (k - 255.5f) * (1.0f / 128.0f);
}

// i0e(x) = exp(-x)*I0(x)
__device__ float i0e_dev(float x) {
    if (x > 8.0f) {
        float invx = 1.0f / x;
        float term = 1.0f, sum = 1.0f;
#pragma unroll
        for (int k = 1; k <= 6; k++) {
            float tk = (float)(2 * k - 1);
            term *= tk * tk * invx * (1.0f / (8.0f * (float)k));
            sum  += term;
        }
        return sum * rsqrtf(2.0f * PI_F * x);
    } else {
        float q = 0.25f * x * x;
        float term = 1.0f, sum = 1.0f;
#pragma unroll
        for (int k = 1; k <= 22; k++) {
            float ik = 1.0f / (float)k;
            term *= q * ik * ik;
            sum  += term;
        }
        return sum * __expf(-x);
    }
}

// ---------------- backprojection ----------------
__global__ void k_bp(const float* __restrict__ proj, const float* __restrict__ tof,
                     const float* __restrict__ x1l, const float* __restrict__ y1l,
                     const float* __restrict__ x1r, const float* __restrict__ y1r,
                     const float* __restrict__ x2l, const float* __restrict__ y2l,
                     const float* __restrict__ x2r, const float* __restrict__ y2r,
                     int n) {
    int e = blockIdx.x * blockDim.x + threadIdx.x;
    if (e >= n) return;

    float x1 = 0.5f * (x1l[e] + x1r[e]);
    float y1 = 0.5f * (y1l[e] + y1r[e]);
    float x2 = 0.5f * (x2l[e] + x2r[e]);
    float y2 = 0.5f * (y2l[e] + y2r[e]);
    float ddx = x2 - x1, ddy = y2 - y1;
    float L = sqrtf(ddx * ddx + ddy * ddy);

    float step     = L * (1.0f / (float)PNS);
    float inv_step = (float)PNS / L;
    float center   = 0.5f * L + 0.15f * tof[e];

    float lo = (center - WIN_NSIG * SIGMA_MM) * inv_step - 0.5f;
    float hi = (center + WIN_NSIG * SIGMA_MM) * inv_step - 0.5f;
    int i0 = max(0,   (int)ceilf(lo));
    int i1 = min(127, (int)floorf(hi));
    if (i0 > i1) return;

    // incremental Gaussian weight
    float dz = step * INV_SIGMA;
    float z0 = (((float)i0 + 0.5f) * step - center) * INV_SIGMA;
    float w  = proj[e] * step * __expf(-0.5f * z0 * z0);
    float r  = __expf(-dz * (z0 + 0.5f * dz));
    float c  = __expf(-dz * dz);

    float* img = g_img[e & (NREP - 1)];   // planar replica plane (distinct LTS slices)

    float t0f = ((float)i0 + 0.5f) * (1.0f / (float)PNS);
    uint64_t t2   = pack2(t0f, t0f);
    uint64_t dt2  = pack2(1.0f / (float)PNS, 1.0f / (float)PNS);
    uint64_t dd2  = pack2(ddx, ddy);
    uint64_t xy2  = pack2(x1, y1);
    uint64_t h2   = pack2(0.5f, 0.5f);
    uint64_t b2   = pack2(128.0f, 128.0f);

#pragma unroll 8
    for (int i = i0; i <= i1; i++) {
        uint64_t pxy = fma2(t2, dd2, xy2);
        uint64_t gxy = fma2(pxy, h2, b2);
        float gx, gy;
        unpack2(gxy, gx, gy);
        int ix = __float2int_rd(gx);
        int iy = __float2int_rd(gy);
        if ((unsigned)(ix | iy) < 256u)
            atomicAdd(&img[iy * PNX + ix], w);
        w *= r;  r *= c;
        t2 = add2(t2, dt2);
    }
}

// ---------------- replica reduction (full-chip, coalesced, float4) ----------------
// 64 blocks x 256 threads: each thread sums 4 contiguous pixels across 64 planes.
__global__ void k_reduce() {
    int p4 = blockIdx.x * blockDim.x + threadIdx.x;   // float4 index [0, 16384)
    float4 acc = make_float4(0.f, 0.f, 0.f, 0.f);
#pragma unroll 8
    for (int rep = 0; rep < NREP; rep++) {
        float4* ptr = (float4*)&g_img[rep][0] + p4;
        float4 v = *ptr;
        acc.x += v.x; acc.y += v.y; acc.z += v.z; acc.w += v.w;
        *ptr = make_float4(0.f, 0.f, 0.f, 0.f);
    }
    ((float4*)g_imgsum)[p4] = acc;
}

// ---------------- fused 2D FFT + filter (persistent; R11 config, verbatim) ----------------
// 128 blocks x 256 threads; 2 line-groups of 128 threads: g = tid>>7, j = tid&127.
__global__ void k_fft_all(float* __restrict__ out) {
    __shared__ float2 A[2][256];
    __shared__ float2 B[2][256];
    __shared__ float2 W[128];
    int g = threadIdx.x >> 7;
    int j = threadIdx.x & 127;
    int line = blockIdx.x * 2 + g;
    fill_twiddles(W, threadIdx.x);

    // ---- Phase A: row forward FFT (coalesced read of reduced image) ----
    {
        int row = line;
        A[g][j]       = make_float2(g_imgsum[row * PNX + j],       0.0f);
        A[g][j + 128] = make_float2(g_imgsum[row * PNX + j + 128], 0.0f);
        __syncthreads();
        fft256(A[g], B[g], W, j, -1.0f);
        g_freq[row * PNX + j]       = A[g][j];
        g_freq[row * PNX + j + 128] = A[g][j + 128];
    }

    grid_barrier(FFT_BLOCKS);

    // ---- Phase B: column fwd FFT -> filter -> column inv FFT ----
    {
        int c = line;
        A[g][j]       = __ldcg(&g_freq[j * PNX + c]);
        A[g][j + 128] = __ldcg(&g_freq[(j + 128) * PNX + c]);
        __syncthreads();
        fft256(A[g], B[g], W, j, -1.0f);

        float fc  = freq_coord(c);
        float fc2 = fc * fc;
#pragma unroll
        for (int kk = j; kk < 256; kk += 128) {
            float fr = freq_coord(kk);
            float w0 = fmaf(fr, fr, fc2);
            float gn = FILT_SCALE / i0e_dev(w0 * FILT_C2);
            A[g][kk].x *= gn;
            A[g][kk].y *= gn;
        }
        __syncthreads();
        fft256(A[g], B[g], W, j, +1.0f);
        g_freq[j * PNX + c]         = A[g][j];
        g_freq[(j + 128) * PNX + c] = A[g][j + 128];
    }

    grid_barrier(FFT_BLOCKS);

    // ---- Phase C: row inverse FFT -> real output ----
    {
        int row = line;
        A[g][j]       = __ldcg(&g_freq[row * PNX + j]);
        A[g][j + 128] = __ldcg(&g_freq[row * PNX + j + 128]);
        __syncthreads();
        fft256(A[g], B[g], W, j, +1.0f);
        out[row * PNX + j]       = A[g][j].x;
        out[row * PNX + j + 128] = A[g][j + 128].x;
    }
}

// ---------------- launch ----------------
extern "C" void kernel_launch(void* const* d_in, const int* in_sizes, int n_in,
                              void* d_out, int out_size) {
    const float* proj = (const float*)d_in[0];
    const float* tof  = (const float*)d_in[1];
    const float* x1l  = (const float*)d_in[2];
    const float* y1l  = (const float*)d_in[3];
    const float* x1r  = (const float*)d_in[4];
    const float* y1r  = (const float*)d_in[5];
    const float* x2l  = (const float*)d_in[6];
    const float* y2l  = (const float*)d_in[7];
    const float* x2r  = (const float*)d_in[8];
    const float* y2r  = (const float*)d_in[9];
    int n = in_sizes[0];

    k_bp<<<(n + 255) / 256, 256>>>(proj, tof, x1l, y1l, x1r, y1r,
                                   x2l, y2l, x2r, y2r, n);
    k_reduce<<<(PNX * PNX) / 4 / 256, 256>>>();
    k_fft_all<<<FFT_BLOCKS, 256>>>((float*)d_out);
}

// round 15
// speedup vs baseline: 1.2198x; 1.1070x over previous
#include <cuda_runtime.h>
#include <cstdint>

// ---------------- static config ----------------
#define PNX 256
#define PNS 128
#define PI_F 3.14159265358979323846f

#define SIGMA_MM   19.108280254777070f
#define INV_SIGMA  (1.0f/19.108280254777070f)
#define FILT_C2    900.91346f
#define FILT_SCALE (1.0f/1024.0f)
#define WIN_NSIG   3.5f
#define NREP       32            // PLANAR replicas: g_img[rep][pixel] (proven optimum)
#define FFT_BLOCKS 128           // BC kernel: 2 lines/block, co-resident

// ---------------- device scratch ----------------
__device__ float  g_img[NREP][PNX * PNX];   // zero-init at load; re-zeroed each call
__device__ float2 g_freq[PNX * PNX];
__device__ unsigned g_bar_count = 0;
__device__ volatile unsigned g_bar_gen = 0;

// ---------------- packed f32x2 helpers (sm_100a) ----------------
__device__ __forceinline__ uint64_t pack2(float lo, float hi) {
    uint64_t r; asm("mov.b64 %0, {%1, %2};" : "=l"(r) : "f"(lo), "f"(hi)); return r;
}
__device__ __forceinline__ void unpack2(uint64_t v, float& lo, float& hi) {
    asm("mov.b64 {%0, %1}, %2;" : "=f"(lo), "=f"(hi) : "l"(v));
}
__device__ __forceinline__ uint64_t fma2(uint64_t a, uint64_t b, uint64_t c) {
    uint64_t r; asm("fma.rn.f32x2 %0, %1, %2, %3;" : "=l"(r) : "l"(a), "l"(b), "l"(c)); return r;
}
__device__ __forceinline__ uint64_t add2(uint64_t a, uint64_t b) {
    uint64_t r; asm("add.rn.f32x2 %0, %1, %2;" : "=l"(r) : "l"(a), "l"(b)); return r;
}

// ---------------- grid barrier (all blocks co-resident) ----------------
__device__ __forceinline__ void grid_barrier(unsigned nblocks) {
    __syncthreads();
    if (threadIdx.x == 0) {
        unsigned gen = g_bar_gen;
        __threadfence();
        if (atomicAdd(&g_bar_count, 1u) == nblocks - 1u) {
            g_bar_count = 0;
            __threadfence();
            g_bar_gen = gen + 1u;
        } else {
            while (g_bar_gen == gen) { }
            __threadfence();
        }
    }
    __syncthreads();
}

// ---------------- FFT helpers (R11 proven config) ----------------
// 256-pt radix-2 Stockham FFT, 128 threads per line, shared twiddles W[128]:
// W[m] = cis(pi*m/128). sign = -1 fwd, +1 inv (unnormalized). Ends in bufA.
__device__ __forceinline__ void fft256(float2* bufA, float2* bufB,
                                       const float2* __restrict__ W,
                                       int j, float sign) {
    float2* x = bufA;
    float2* y = bufB;
#pragma unroll
    for (int st = 0; st < 8; st++) {
        int Ns = 1 << st;
        float2 v0 = x[j];
        float2 v1 = x[j + 128];
        int k = j & (Ns - 1);
        float2 w = W[k << (7 - st)];
        float wy = sign * w.y;
        float2 tv = make_float2(v1.x * w.x - v1.y * wy,
                                v1.x * wy + v1.y * w.x);
        int id = ((j - k) << 1) + k;
        y[id]      = make_float2(v0.x + tv.x, v0.y + tv.y);
        y[id + Ns] = make_float2(v0.x - tv.x, v0.y - tv.y);
        __syncthreads();
        float2* t = x; x = y; y = t;
    }
}

__device__ __forceinline__ void fill_twiddles(float2* W, int tid) {
    if (tid < 128) {
        float s, c;
        sincospif((float)tid * (1.0f / 128.0f), &s, &c);
        W[tid] = make_float2(c, s);
    }
}

__device__ __forceinline__ float freq_coord(int k) {
    return (k < 128) ? (k + 0.5f) * (1.0f / 128.0f)
                     : (k - 255.5f) * (1.0f / 128.0f);
}

// i0e(x) = exp(-x)*I0(x)
__device__ float i0e_dev(float x) {
    if (x > 8.0f) {
        float invx = 1.0f / x;
        float term = 1.0f, sum = 1.0f;
#pragma unroll
        for (int k = 1; k <= 6; k++) {
            float tk = (float)(2 * k - 1);
            term *= tk * tk * invx * (1.0f / (8.0f * (float)k));
            sum  += term;
        }
        return sum * rsqrtf(2.0f * PI_F * x);
    } else {
        float q = 0.25f * x * x;
        float term = 1.0f, sum = 1.0f;
#pragma unroll
        for (int k = 1; k <= 22; k++) {
            float ik = 1.0f / (float)k;
            term *= q * ik * ik;
            sum  += term;
        }
        return sum * __expf(-x);
    }
}

// ---------------- backprojection (R11 verbatim — at floor) ----------------
__global__ void k_bp(const float* __restrict__ proj, const float* __restrict__ tof,
                     const float* __restrict__ x1l, const float* __restrict__ y1l,
                     const float* __restrict__ x1r, const float* __restrict__ y1r,
                     const float* __restrict__ x2l, const float* __restrict__ y2l,
                     const float* __restrict__ x2r, const float* __restrict__ y2r,
                     int n) {
    int e = blockIdx.x * blockDim.x + threadIdx.x;
    if (e >= n) return;

    float x1 = 0.5f * (x1l[e] + x1r[e]);
    float y1 = 0.5f * (y1l[e] + y1r[e]);
    float x2 = 0.5f * (x2l[e] + x2r[e]);
    float y2 = 0.5f * (y2l[e] + y2r[e]);
    float ddx = x2 - x1, ddy = y2 - y1;
    float L = sqrtf(ddx * ddx + ddy * ddy);

    float step     = L * (1.0f / (float)PNS);
    float inv_step = (float)PNS / L;
    float center   = 0.5f * L + 0.15f * tof[e];

    float lo = (center - WIN_NSIG * SIGMA_MM) * inv_step - 0.5f;
    float hi = (center + WIN_NSIG * SIGMA_MM) * inv_step - 0.5f;
    int i0 = max(0,   (int)ceilf(lo));
    int i1 = min(127, (int)floorf(hi));
    if (i0 > i1) return;

    // incremental Gaussian weight
    float dz = step * INV_SIGMA;
    float z0 = (((float)i0 + 0.5f) * step - center) * INV_SIGMA;
    float w  = proj[e] * step * __expf(-0.5f * z0 * z0);
    float r  = __expf(-dz * (z0 + 0.5f * dz));
    float c  = __expf(-dz * dz);

    float* img = g_img[e & (NREP - 1)];   // planar replica plane

    float t0f = ((float)i0 + 0.5f) * (1.0f / (float)PNS);
    uint64_t t2   = pack2(t0f, t0f);
    uint64_t dt2  = pack2(1.0f / (float)PNS, 1.0f / (float)PNS);
    uint64_t dd2  = pack2(ddx, ddy);
    uint64_t xy2  = pack2(x1, y1);
    uint64_t h2   = pack2(0.5f, 0.5f);
    uint64_t b2   = pack2(128.0f, 128.0f);

#pragma unroll 8
    for (int i = i0; i <= i1; i++) {
        uint64_t pxy = fma2(t2, dd2, xy2);
        uint64_t gxy = fma2(pxy, h2, b2);
        float gx, gy;
        unpack2(gxy, gx, gy);
        int ix = __float2int_rd(gx);
        int iy = __float2int_rd(gy);
        if ((unsigned)(ix | iy) < 256u)
            atomicAdd(&img[iy * PNX + ix], w);
        w *= r;  r *= c;
        t2 = add2(t2, dt2);
    }
}

// ---------------- fused replica-reduction + row forward FFT ----------------
// 256 blocks x 128 threads: one block per image row. Each thread sums the 32
// planar replicas for its 2 pixels (coalesced per plane), zeroes them, then
// the block row-FFTs and stores to g_freq. Full-chip parallelism, no barriers.
__global__ void k_reduce_fftA() {
    __shared__ float2 A[256];
    __shared__ float2 B[256];
    __shared__ float2 W[128];
    int row = blockIdx.x;
    int j   = threadIdx.x;
    fill_twiddles(W, j);

    int idx0 = row * PNX + j;
    int idx1 = idx0 + 128;
    float a0 = 0.0f, a1 = 0.0f;
#pragma unroll 8
    for (int rep = 0; rep < NREP; rep++) {
        a0 += g_img[rep][idx0];
        a1 += g_img[rep][idx1];
        g_img[rep][idx0] = 0.0f;
        g_img[rep][idx1] = 0.0f;
    }
    A[j]       = make_float2(a0, 0.0f);
    A[j + 128] = make_float2(a1, 0.0f);
    __syncthreads();
    fft256(A, B, W, j, -1.0f);
    g_freq[row * PNX + j]       = A[j];
    g_freq[row * PNX + j + 128] = A[j + 128];
}

// ---------------- fused col FFT + filter + inv col FFT + inv row FFT ----------------
// 128 blocks x 256 threads; 2 line-groups of 128 threads (R11 shape), 1 barrier.
__global__ void k_fft_BC(float* __restrict__ out) {
    __shared__ float2 A[2][256];
    __shared__ float2 B[2][256];
    __shared__ float2 W[128];
    int g = threadIdx.x >> 7;
    int j = threadIdx.x & 127;
    int line = blockIdx.x * 2 + g;
    fill_twiddles(W, threadIdx.x);

    // ---- Phase B: column fwd FFT -> filter -> column inv FFT ----
    {
        int c = line;
        A[g][j]       = g_freq[j * PNX + c];
        A[g][j + 128] = g_freq[(j + 128) * PNX + c];
        __syncthreads();
        fft256(A[g], B[g], W, j, -1.0f);

        float fc  = freq_coord(c);
        float fc2 = fc * fc;
#pragma unroll
        for (int kk = j; kk < 256; kk += 128) {
            float fr = freq_coord(kk);
            float w0 = fmaf(fr, fr, fc2);
            float gn = FILT_SCALE / i0e_dev(w0 * FILT_C2);
            A[g][kk].x *= gn;
            A[g][kk].y *= gn;
        }
        __syncthreads();
        fft256(A[g], B[g], W, j, +1.0f);
        g_freq[j * PNX + c]         = A[g][j];
        g_freq[(j + 128) * PNX + c] = A[g][j + 128];
    }

    grid_barrier(FFT_BLOCKS);

    // ---- Phase C: row inverse FFT -> real output ----
    {
        int row = line;
        A[g][j]       = __ldcg(&g_freq[row * PNX + j]);
        A[g][j + 128] = __ldcg(&g_freq[row * PNX + j + 128]);
        __syncthreads();
        fft256(A[g], B[g], W, j, +1.0f);
        out[row * PNX + j]       = A[g][j].x;
        out[row * PNX + j + 128] = A[g][j + 128].x;
    }
}

// ---------------- launch ----------------
extern "C" void kernel_launch(void* const* d_in, const int* in_sizes, int n_in,
                              void* d_out, int out_size) {
    const float* proj = (const float*)d_in[0];
    const float* tof  = (const float*)d_in[1];
    const float* x1l  = (const float*)d_in[2];
    const float* y1l  = (const float*)d_in[3];
    const float* x1r  = (const float*)d_in[4];
    const float* y1r  = (const float*)d_in[5];
    const float* x2l  = (const float*)d_in[6];
    const float* y2l  = (const float*)d_in[7];
    const float* x2r  = (const float*)d_in[8];
    const float* y2r  = (const float*)d_in[9];
    int n = in_sizes[0];

    k_bp<<<(n + 255) / 256, 256>>>(proj, tof, x1l, y1l, x1r, y1r,
                                   x2l, y2l, x2r, y2r, n);
    k_reduce_fftA<<<PNX, 128>>>();
    k_fft_BC<<<FFT_BLOCKS, 256>>>((float*)d_out);
}

// round 16
// speedup vs baseline: 1.2235x; 1.0030x over previous
#include <cuda_runtime.h>
#include <cstdint>

// ---------------- static config ----------------
#define PNX 256
#define PNS 128
#define PI_F 3.14159265358979323846f

#define SIGMA_MM   19.108280254777070f
#define INV_SIGMA  (1.0f/19.108280254777070f)
#define FILT_C2    900.91346f
#define FILT_SCALE (1.0f/1024.0f)
#define WIN_NSIG   3.5f
#define NREP       32            // PLANAR replicas: g_img[rep][pixel] (proven optimum)
#define FFT_BLOCKS 128           // BC kernel: 2 lines/block, co-resident

// ---------------- device scratch ----------------
__device__ float  g_img[NREP][PNX * PNX];   // zero-init at load; re-zeroed each call
__device__ float2 g_freqT[PNX * PNX];       // row-spectrum TRANSPOSED: [kx][row]
__device__ float2 g_freq[PNX * PNX];        // filtered spectrum: [row][kx]
__device__ unsigned g_bar_count = 0;
__device__ volatile unsigned g_bar_gen = 0;

// ---------------- packed f32x2 helpers (sm_100a) ----------------
__device__ __forceinline__ uint64_t pack2(float lo, float hi) {
    uint64_t r; asm("mov.b64 %0, {%1, %2};" : "=l"(r) : "f"(lo), "f"(hi)); return r;
}
__device__ __forceinline__ void unpack2(uint64_t v, float& lo, float& hi) {
    asm("mov.b64 {%0, %1}, %2;" : "=f"(lo), "=f"(hi) : "l"(v));
}
__device__ __forceinline__ uint64_t fma2(uint64_t a, uint64_t b, uint64_t c) {
    uint64_t r; asm("fma.rn.f32x2 %0, %1, %2, %3;" : "=l"(r) : "l"(a), "l"(b), "l"(c)); return r;
}
__device__ __forceinline__ uint64_t add2(uint64_t a, uint64_t b) {
    uint64_t r; asm("add.rn.f32x2 %0, %1, %2;" : "=l"(r) : "l"(a), "l"(b)); return r;
}

// ---------------- grid barrier (all blocks co-resident) ----------------
__device__ __forceinline__ void grid_barrier(unsigned nblocks) {
    __syncthreads();
    if (threadIdx.x == 0) {
        unsigned gen = g_bar_gen;
        __threadfence();
        if (atomicAdd(&g_bar_count, 1u) == nblocks - 1u) {
            g_bar_count = 0;
            __threadfence();
            g_bar_gen = gen + 1u;
        } else {
            while (g_bar_gen == gen) { }
            __threadfence();
        }
    }
    __syncthreads();
}

// ---------------- FFT helpers (R11 proven config) ----------------
// 256-pt radix-2 Stockham FFT, 128 threads per line, shared twiddles W[128]:
// W[m] = cis(pi*m/128). sign = -1 fwd, +1 inv (unnormalized). Ends in bufA.
__device__ __forceinline__ void fft256(float2* bufA, float2* bufB,
                                       const float2* __restrict__ W,
                                       int j, float sign) {
    float2* x = bufA;
    float2* y = bufB;
#pragma unroll
    for (int st = 0; st < 8; st++) {
        int Ns = 1 << st;
        float2 v0 = x[j];
        float2 v1 = x[j + 128];
        int k = j & (Ns - 1);
        float2 w = W[k << (7 - st)];
        float wy = sign * w.y;
        float2 tv = make_float2(v1.x * w.x - v1.y * wy,
                                v1.x * wy + v1.y * w.x);
        int id = ((j - k) << 1) + k;
        y[id]      = make_float2(v0.x + tv.x, v0.y + tv.y);
        y[id + Ns] = make_float2(v0.x - tv.x, v0.y - tv.y);
        __syncthreads();
        float2* t = x; x = y; y = t;
    }
}

__device__ __forceinline__ void fill_twiddles(float2* W, int tid) {
    if (tid < 128) {
        float s, c;
        sincospif((float)tid * (1.0f / 128.0f), &s, &c);
        W[tid] = make_float2(c, s);
    }
}

__device__ __forceinline__ float freq_coord(int k) {
    return (k < 128) ? (k + 0.5f) * (1.0f / 128.0f)
                     : (k - 255.5f) * (1.0f / 128.0f);
}

// i0e(x) = exp(-x)*I0(x)
__device__ float i0e_dev(float x) {
    if (x > 8.0f) {
        float invx = 1.0f / x;
        float term = 1.0f, sum = 1.0f;
#pragma unroll
        for (int k = 1; k <= 6; k++) {
            float tk = (float)(2 * k - 1);
            term *= tk * tk * invx * (1.0f / (8.0f * (float)k));
            sum  += term;
        }
        return sum * rsqrtf(2.0f * PI_F * x);
    } else {
        float q = 0.25f * x * x;
        float term = 1.0f, sum = 1.0f;
#pragma unroll
        for (int k = 1; k <= 22; k++) {
            float ik = 1.0f / (float)k;
            term *= q * ik * ik;
            sum  += term;
        }
        return sum * __expf(-x);
    }
}

// ---------------- backprojection (at REDG floor; 128-thread blocks for tail) ----------------
__global__ void k_bp(const float* __restrict__ proj, const float* __restrict__ tof,
                     const float* __restrict__ x1l, const float* __restrict__ y1l,
                     const float* __restrict__ x1r, const float* __restrict__ y1r,
                     const float* __restrict__ x2l, const float* __restrict__ y2l,
                     const float* __restrict__ x2r, const float* __restrict__ y2r,
                     int n) {
    int e = blockIdx.x * blockDim.x + threadIdx.x;
    if (e >= n) return;

    float x1 = 0.5f * (x1l[e] + x1r[e]);
    float y1 = 0.5f * (y1l[e] + y1r[e]);
    float x2 = 0.5f * (x2l[e] + x2r[e]);
    float y2 = 0.5f * (y2l[e] + y2r[e]);
    float ddx = x2 - x1, ddy = y2 - y1;
    float L = sqrtf(ddx * ddx + ddy * ddy);

    float step     = L * (1.0f / (float)PNS);
    float inv_step = (float)PNS / L;
    float center   = 0.5f * L + 0.15f * tof[e];

    float lo = (center - WIN_NSIG * SIGMA_MM) * inv_step - 0.5f;
    float hi = (center + WIN_NSIG * SIGMA_MM) * inv_step - 0.5f;
    int i0 = max(0,   (int)ceilf(lo));
    int i1 = min(127, (int)floorf(hi));
    if (i0 > i1) return;

    // incremental Gaussian weight
    float dz = step * INV_SIGMA;
    float z0 = (((float)i0 + 0.5f) * step - center) * INV_SIGMA;
    float w  = proj[e] * step * __expf(-0.5f * z0 * z0);
    float r  = __expf(-dz * (z0 + 0.5f * dz));
    float c  = __expf(-dz * dz);

    float* img = g_img[e & (NREP - 1)];   // planar replica plane

    float t0f = ((float)i0 + 0.5f) * (1.0f / (float)PNS);
    uint64_t t2   = pack2(t0f, t0f);
    uint64_t dt2  = pack2(1.0f / (float)PNS, 1.0f / (float)PNS);
    uint64_t dd2  = pack2(ddx, ddy);
    uint64_t xy2  = pack2(x1, y1);
    uint64_t h2   = pack2(0.5f, 0.5f);
    uint64_t b2   = pack2(128.0f, 128.0f);

#pragma unroll 8
    for (int i = i0; i <= i1; i++) {
        uint64_t pxy = fma2(t2, dd2, xy2);
        uint64_t gxy = fma2(pxy, h2, b2);
        float gx, gy;
        unpack2(gxy, gx, gy);
        int ix = __float2int_rd(gx);
        int iy = __float2int_rd(gy);
        if ((unsigned)(ix | iy) < 256u)
            atomicAdd(&img[iy * PNX + ix], w);
        w *= r;  r *= c;
        t2 = add2(t2, dt2);
    }
}

// ---------------- fused replica-reduction + row forward FFT (transpose-on-store) ----------------
// 256 blocks x 128 threads: one block per image row. Sum 32 planar replicas
// (coalesced per plane), zero them, row-FFT, store spectrum TRANSPOSED so the
// next kernel's loads are coalesced (scattered stores are fire-and-forget).
__global__ void k_reduce_fftA() {
    __shared__ float2 A[256];
    __shared__ float2 B[256];
    __shared__ float2 W[128];
    int row = blockIdx.x;
    int j   = threadIdx.x;
    fill_twiddles(W, j);

    int idx0 = row * PNX + j;
    int idx1 = idx0 + 128;
    float a0 = 0.0f, a1 = 0.0f;
#pragma unroll 8
    for (int rep = 0; rep < NREP; rep++) {
        a0 += g_img[rep][idx0];
        a1 += g_img[rep][idx1];
        g_img[rep][idx0] = 0.0f;
        g_img[rep][idx1] = 0.0f;
    }
    A[j]       = make_float2(a0, 0.0f);
    A[j + 128] = make_float2(a1, 0.0f);
    __syncthreads();
    fft256(A, B, W, j, -1.0f);
    g_freqT[j * PNX + row]         = A[j];          // scattered store
    g_freqT[(j + 128) * PNX + row] = A[j + 128];
}

// ---------------- fused col FFT + filter + inv col FFT + inv row FFT ----------------
// 128 blocks x 256 threads; 2 line-groups of 128 threads, 1 grid barrier.
// ALL loads coalesced; striding lives in stores only.
__global__ void k_fft_BC(float* __restrict__ out) {
    __shared__ float2 A[2][256];
    __shared__ float2 B[2][256];
    __shared__ float2 W[128];
    int g = threadIdx.x >> 7;
    int j = threadIdx.x & 127;
    int line = blockIdx.x * 2 + g;
    fill_twiddles(W, threadIdx.x);

    // ---- Phase B: column fwd FFT -> filter -> column inv FFT ----
    {
        int c = line;
        A[g][j]       = g_freqT[c * PNX + j];        // coalesced load
        A[g][j + 128] = g_freqT[c * PNX + j + 128];
        __syncthreads();
        fft256(A[g], B[g], W, j, -1.0f);

        float fc  = freq_coord(c);
        float fc2 = fc * fc;
#pragma unroll
        for (int kk = j; kk < 256; kk += 128) {
            float fr = freq_coord(kk);
            float w0 = fmaf(fr, fr, fc2);
            float gn = FILT_SCALE / i0e_dev(w0 * FILT_C2);
            A[g][kk].x *= gn;
            A[g][kk].y *= gn;
        }
        __syncthreads();
        fft256(A[g], B[g], W, j, +1.0f);
        g_freq[j * PNX + c]         = A[g][j];       // scattered store
        g_freq[(j + 128) * PNX + c] = A[g][j + 128];
    }

    grid_barrier(FFT_BLOCKS);

    // ---- Phase C: row inverse FFT -> real output (coalesced) ----
    {
        int row = line;
        A[g][j]       = __ldcg(&g_freq[row * PNX + j]);       // bypass stale L1
        A[g][j + 128] = __ldcg(&g_freq[row * PNX + j + 128]);
        __syncthreads();
        fft256(A[g], B[g], W, j, +1.0f);
        out[row * PNX + j]       = A[g][j].x;
        out[row * PNX + j + 128] = A[g][j + 128].x;
    }
}

// ---------------- launch ----------------
extern "C" void kernel_launch(void* const* d_in, const int* in_sizes, int n_in,
                              void* d_out, int out_size) {
    const float* proj = (const float*)d_in[0];
    const float* tof  = (const float*)d_in[1];
    const float* x1l  = (const float*)d_in[2];
    const float* y1l  = (const float*)d_in[3];
    const float* x1r  = (const float*)d_in[4];
    const float* y1r  = (const float*)d_in[5];
    const float* x2l  = (const float*)d_in[6];
    const float* y2l  = (const float*)d_in[7];
    const float* x2r  = (const float*)d_in[8];
    const float* y2r  = (const float*)d_in[9];
    int n = in_sizes[0];

    k_bp<<<(n + 127) / 128, 128>>>(proj, tof, x1l, y1l, x1r, y1r,
                                   x2l, y2l, x2r, y2r, n);
    k_reduce_fftA<<<PNX, 128>>>();
    k_fft_BC<<<FFT_BLOCKS, 256>>>((float*)d_out);
}

// round 17
// speedup vs baseline: 1.2994x; 1.0620x over previous
#include <cuda_runtime.h>
#include <cstdint>

// ---------------- static config ----------------
#define PNX 256
#define PNS 128
#define PI_F 3.14159265358979323846f

#define SIGMA_MM   19.108280254777070f
#define INV_SIGMA  (1.0f/19.108280254777070f)
#define FILT_C2    900.91346f
#define FILT_SCALE (1.0f/1024.0f)
#define WIN_NSIG   3.5f
#define NREP       32            // PLANAR replicas (proven optimum)
#define BSTRIDE    132           // row stride of g_freqB (129 cols padded)

// ---------------- device scratch ----------------
__device__ float  g_img[NREP][PNX * PNX];   // zero-init at load; re-zeroed each call
__device__ float2 g_freqT[129 * PNX];       // F(kx,row): [kx][row], kx = 0..128
__device__ float2 g_freqB[PNX * BSTRIDE];   // g(kx,y): [y][kx], kx = 0..128

// ---------------- packed f32x2 helpers (sm_100a) ----------------
__device__ __forceinline__ uint64_t pack2(float lo, float hi) {
    uint64_t r; asm("mov.b64 %0, {%1, %2};" : "=l"(r) : "f"(lo), "f"(hi)); return r;
}
__device__ __forceinline__ void unpack2(uint64_t v, float& lo, float& hi) {
    asm("mov.b64 {%0, %1}, %2;" : "=f"(lo), "=f"(hi) : "l"(v));
}
__device__ __forceinline__ uint64_t fma2(uint64_t a, uint64_t b, uint64_t c) {
    uint64_t r; asm("fma.rn.f32x2 %0, %1, %2, %3;" : "=l"(r) : "l"(a), "l"(b), "l"(c)); return r;
}
__device__ __forceinline__ uint64_t add2(uint64_t a, uint64_t b) {
    uint64_t r; asm("add.rn.f32x2 %0, %1, %2;" : "=l"(r) : "l"(a), "l"(b)); return r;
}

// ---------------- FFT helpers (proven config) ----------------
// 256-pt radix-2 Stockham FFT, 128 threads per line, shared twiddles W[128]:
// W[m] = cis(pi*m/128). sign = -1 fwd, +1 inv (unnormalized). Ends in bufA.
__device__ __forceinline__ void fft256(float2* bufA, float2* bufB,
                                       const float2* __restrict__ W,
                                       int j, float sign) {
    float2* x = bufA;
    float2* y = bufB;
#pragma unroll
    for (int st = 0; st < 8; st++) {
        int Ns = 1 << st;
        float2 v0 = x[j];
        float2 v1 = x[j + 128];
        int k = j & (Ns - 1);
        float2 w = W[k << (7 - st)];
        float wy = sign * w.y;
        float2 tv = make_float2(v1.x * w.x - v1.y * wy,
                                v1.x * wy + v1.y * w.x);
        int id = ((j - k) << 1) + k;
        y[id]      = make_float2(v0.x + tv.x, v0.y + tv.y);
        y[id + Ns] = make_float2(v0.x - tv.x, v0.y - tv.y);
        __syncthreads();
        float2* t = x; x = y; y = t;
    }
}

__device__ __forceinline__ void fill_twiddles(float2* W, int tid) {
    if (tid < 128) {
        float s, c;
        sincospif((float)tid * (1.0f / 128.0f), &s, &c);
        W[tid] = make_float2(c, s);
    }
}

__device__ __forceinline__ float freq_coord(int k) {
    return (k < 128) ? (k + 0.5f) * (1.0f / 128.0f)
                     : (k - 255.5f) * (1.0f / 128.0f);
}

// i0e(x) = exp(-x)*I0(x)
__device__ float i0e_dev(float x) {
    if (x > 8.0f) {
        float invx = 1.0f / x;
        float term = 1.0f, sum = 1.0f;
#pragma unroll
        for (int k = 1; k <= 6; k++) {
            float tk = (float)(2 * k - 1);
            term *= tk * tk * invx * (1.0f / (8.0f * (float)k));
            sum  += term;
        }
        return sum * rsqrtf(2.0f * PI_F * x);
    } else {
        float q = 0.25f * x * x;
        float term = 1.0f, sum = 1.0f;
#pragma unroll
        for (int k = 1; k <= 22; k++) {
            float ik = 1.0f / (float)k;
            term *= q * ik * ik;
            sum  += term;
        }
        return sum * __expf(-x);
    }
}

// ---------------- backprojection (at REDG floor; unchanged) ----------------
__global__ void k_bp(const float* __restrict__ proj, const float* __restrict__ tof,
                     const float* __restrict__ x1l, const float* __restrict__ y1l,
                     const float* __restrict__ x1r, const float* __restrict__ y1r,
                     const float* __restrict__ x2l, const float* __restrict__ y2l,
                     const float* __restrict__ x2r, const float* __restrict__ y2r,
                     int n) {
    int e = blockIdx.x * blockDim.x + threadIdx.x;
    if (e >= n) return;

    float x1 = 0.5f * (x1l[e] + x1r[e]);
    float y1 = 0.5f * (y1l[e] + y1r[e]);
    float x2 = 0.5f * (x2l[e] + x2r[e]);
    float y2 = 0.5f * (y2l[e] + y2r[e]);
    float ddx = x2 - x1, ddy = y2 - y1;
    float L = sqrtf(ddx * ddx + ddy * ddy);

    float step     = L * (1.0f / (float)PNS);
    float inv_step = (float)PNS / L;
    float center   = 0.5f * L + 0.15f * tof[e];

    float lo = (center - WIN_NSIG * SIGMA_MM) * inv_step - 0.5f;
    float hi = (center + WIN_NSIG * SIGMA_MM) * inv_step - 0.5f;
    int i0 = max(0,   (int)ceilf(lo));
    int i1 = min(127, (int)floorf(hi));
    if (i0 > i1) return;

    // incremental Gaussian weight
    float dz = step * INV_SIGMA;
    float z0 = (((float)i0 + 0.5f) * step - center) * INV_SIGMA;
    float w  = proj[e] * step * __expf(-0.5f * z0 * z0);
    float r  = __expf(-dz * (z0 + 0.5f * dz));
    float c  = __expf(-dz * dz);

    float* img = g_img[e & (NREP - 1)];   // planar replica plane

    float t0f = ((float)i0 + 0.5f) * (1.0f / (float)PNS);
    uint64_t t2   = pack2(t0f, t0f);
    uint64_t dt2  = pack2(1.0f / (float)PNS, 1.0f / (float)PNS);
    uint64_t dd2  = pack2(ddx, ddy);
    uint64_t xy2  = pack2(x1, y1);
    uint64_t h2   = pack2(0.5f, 0.5f);
    uint64_t b2   = pack2(128.0f, 128.0f);

#pragma unroll 8
    for (int i = i0; i <= i1; i++) {
        uint64_t pxy = fma2(t2, dd2, xy2);
        uint64_t gxy = fma2(pxy, h2, b2);
        float gx, gy;
        unpack2(gxy, gx, gy);
        int ix = __float2int_rd(gx);
        int iy = __float2int_rd(gy);
        if ((unsigned)(ix | iy) < 256u)
            atomicAdd(&img[iy * PNX + ix], w);
        w *= r;  r *= c;
        t2 = add2(t2, dt2);
    }
}

// ---------------- Phase A: replica-sum + packed DOUBLE-row forward FFT ----------------
// 128 blocks x 128 threads: block m packs rows 2m (re) and 2m+1 (im) into one
// complex FFT; unpacks Fa(k)=0.5(Z(k)+conj(Z(-k))), Fb(k)=-i/2(Z(k)-conj(Z(-k))).
// Stores ONLY kx=0..128 (Hermitian half), transposed, as one float4 per thread.
__global__ void k_fftA() {
    __shared__ float2 A[256];
    __shared__ float2 B[256];
    __shared__ float2 W[128];
    int m = blockIdx.x, j = threadIdx.x;
    int ra = 2 * m;
    fill_twiddles(W, j);

    int ia0 = ra * PNX + j, ia1 = ia0 + 128;
    int ib0 = ia0 + PNX,    ib1 = ia1 + PNX;
    float sa0 = 0.f, sa1 = 0.f, sb0 = 0.f, sb1 = 0.f;
#pragma unroll 8
    for (int rep = 0; rep < NREP; rep++) {
        sa0 += g_img[rep][ia0];  g_img[rep][ia0] = 0.f;
        sa1 += g_img[rep][ia1];  g_img[rep][ia1] = 0.f;
        sb0 += g_img[rep][ib0];  g_img[rep][ib0] = 0.f;
        sb1 += g_img[rep][ib1];  g_img[rep][ib1] = 0.f;
    }
    A[j]       = make_float2(sa0, sb0);
    A[j + 128] = make_float2(sa1, sb1);
    __syncthreads();
    fft256(A, B, W, j, -1.0f);

    // unpack k = j  (mirror index (256-j)&255)
    float2 P = A[j];
    float2 Q = A[(256 - j) & 255];
    float fax = 0.5f * (P.x + Q.x), fay = 0.5f * (P.y - Q.y);
    float fbx = 0.5f * (P.y + Q.y), fby = 0.5f * (Q.x - P.x);
    *(float4*)&g_freqT[j * PNX + ra] = make_float4(fax, fay, fbx, fby);
    if (j == 0) {   // k = 128 (self-mirror): Fa=(Z.x,0), Fb=(Z.y,0)
        float2 Pn = A[128];
        *(float4*)&g_freqT[128 * PNX + ra] = make_float4(Pn.x, 0.f, Pn.y, 0.f);
    }
}

// ---------------- Phase B: half-spectrum column FFT + symmetrized filter + inv ----------------
// 129 blocks x 128 threads: column kx = c in [0,128]. Filter applied is
// Hs(k) = 0.5*(H(k) + H(-k)) — exact equivalent of the reference's final .real.
__global__ void k_fftB() {
    __shared__ float2 A[256];
    __shared__ float2 B[256];
    __shared__ float2 W[128];
    int c = blockIdx.x, j = threadIdx.x;
    fill_twiddles(W, j);

    A[j]       = g_freqT[c * PNX + j];         // coalesced
    A[j + 128] = g_freqT[c * PNX + j + 128];
    __syncthreads();
    fft256(A, B, W, j, -1.0f);

    int   cm   = (256 - c) & 255;
    float fx   = freq_coord(c),  fxm  = freq_coord(cm);
    float fx2  = fx * fx,        fxm2 = fxm * fxm;
#pragma unroll
    for (int kk = j; kk < 256; kk += 128) {
        float fy  = freq_coord(kk);
        float fym = freq_coord((256 - kk) & 255);
        float w1  = fmaf(fy,  fy,  fx2);
        float w2  = fmaf(fym, fym, fxm2);
        float gn  = (0.5f * FILT_SCALE) *
                    (1.0f / i0e_dev(w1 * FILT_C2) + 1.0f / i0e_dev(w2 * FILT_C2));
        A[kk].x *= gn;
        A[kk].y *= gn;
    }
    __syncthreads();
    fft256(A, B, W, j, +1.0f);
    g_freqB[j * BSTRIDE + c]         = A[j];    // scattered store (fire-and-forget)
    g_freqB[(j + 128) * BSTRIDE + c] = A[j + 128];
}

// ---------------- Phase C: Hermitian synthesis + packed DOUBLE-row inverse FFT ----------------
// 128 blocks x 128 threads: block m builds Z(k) = Ga_full(k) + i*Gb_full(k)
// from half-spectra of rows 2m, 2m+1 (mirror-conj for k>128); one inverse FFT
// yields both real output rows: Re -> row 2m, Im -> row 2m+1.
__global__ void k_fftC(float* __restrict__ out) {
    __shared__ float2 A[256];
    __shared__ float2 B[256];
    __shared__ float2 W[128];
    __shared__ float2 Ga[129];
    __shared__ float2 Gb[129];
    int m = blockIdx.x, j = threadIdx.x;
    int ra = 2 * m, rb = ra + 1;
    fill_twiddles(W, j);

    Ga[j] = g_freqB[ra * BSTRIDE + j];          // coalesced
    Gb[j] = g_freqB[rb * BSTRIDE + j];
    if (j == 0) {
        Ga[128] = g_freqB[ra * BSTRIDE + 128];
        Gb[128] = g_freqB[rb * BSTRIDE + 128];
    }
    __syncthreads();

    // Z(k) for k = j (direct) and k = j+128 (mirror-conj unless j==0)
    A[j] = make_float2(Ga[j].x - Gb[j].y, Ga[j].y + Gb[j].x);
    if (j == 0) {
        A[128] = make_float2(Ga[128].x - Gb[128].y, Ga[128].y + Gb[128].x);
    } else {
        int mm = 128 - j;   // 256 - (j+128)
        A[j + 128] = make_float2(Ga[mm].x + Gb[mm].y, Gb[mm].x - Ga[mm].y);
    }
    __syncthreads();
    fft256(A, B, W, j, +1.0f);

    out[ra * PNX + j]       = A[j].x;
    out[ra * PNX + j + 128] = A[j + 128].x;
    out[rb * PNX + j]       = A[j].y;
    out[rb * PNX + j + 128] = A[j + 128].y;
}

// ---------------- launch ----------------
extern "C" void kernel_launch(void* const* d_in, const int* in_sizes, int n_in,
                              void* d_out, int out_size) {
    const float* proj = (const float*)d_in[0];
    const float* tof  = (const float*)d_in[1];
    const float* x1l  = (const float*)d_in[2];
    const float* y1l  = (const float*)d_in[3];
    const float* x1r  = (const float*)d_in[4];
    const float* y1r  = (const float*)d_in[5];
    const float* x2l  = (const float*)d_in[6];
    const float* y2l  = (const float*)d_in[7];
    const float* x2r  = (const float*)d_in[8];
    const float* y2r  = (const float*)d_in[9];
    int n = in_sizes[0];

    k_bp<<<(n + 127) / 128, 128>>>(proj, tof, x1l, y1l, x1r, y1r,
                                   x2l, y2l, x2r, y2r, n);
    k_fftA<<<PNX / 2, 128>>>();
    k_fftB<<<129, 128>>>();
    k_fftC<<<PNX / 2, 128>>>((float*)d_out);
}